// round 5
// baseline (speedup 1.0000x reference)
#include <cuda_runtime.h>

#define OMEGA_W 0.9f
#define N0 2048
#define N1 1024
#define N2 512
#define N3 256

// Scratch (device globals — no allocation allowed).
__device__ float g_u0b[N0 * N0];
__device__ float g_u0c[N0 * N0];
__device__ float g_u1a[N1 * N1];
__device__ float g_u1b[N1 * N1];
__device__ float g_r1[N1 * N1];
__device__ float g_u2a[N2 * N2];
__device__ float g_u2b[N2 * N2];
__device__ float g_r2[N2 * N2];
__device__ float g_u3a[N3 * N3];
__device__ float g_u3b[N3 * N3];
__device__ float g_r3[N3 * N3];

// Staged-array index helpers (offsets bake in the halo origin).
#define IDX69(y, x) (((y) + 3) * 69 + ((x) + 3))   // coeff tile 21x69, y:-3..17, x:-3..65
#define IDX68(y, x) (((y) + 2) * 68 + ((x) + 2))   // halo-2 tile 20x68, y:-2..17, x:-2..65
#define IDX66(y, x) (((y) + 1) * 66 + ((x) + 1))   // halo-1 tile 18x66, y:-1..16, x:-1..64
#define IDX70(y, x) (((y) + 3) * 70 + ((x) + 3))   // u tile 22x70,    y:-3..18, x:-3..66
#define IDXE(jy, jx) (((jy) + 2) * 36 + ((jx) + 2)) // coarse e tile 12x36 (rel coords)

// ===========================================================================
// jrr0: u==0 start. Stage cx/cy/rhs -> winv + sweep1 (local) -> sweep2 ->
// store u + residual + restrict. Block (32,8), owned fine tile 64x16.
// ===========================================================================
__global__ __launch_bounds__(256)
void jrr0_kernel(const float* __restrict__ rhs,
                 const float* __restrict__ cx,
                 const float* __restrict__ cy,
                 float* __restrict__ udst,
                 float* __restrict__ rc, int n, float ih2) {
    __shared__ float s_cx[21 * 69], s_cy[21 * 69];
    __shared__ float s_rh[20 * 68], s_iv[20 * 68], s_1[20 * 68];
    __shared__ float s_2[18 * 66];
    const int tx = threadIdx.x, ty = threadIdx.y;
    const int tid = ty * 32 + tx;
    const int bx0 = blockIdx.x * 64, by0 = blockIdx.y * 16;

    for (int sp = tid; sp < 21 * 69; sp += 256) {
        int gy = by0 + sp / 69 - 3, gx = bx0 + sp % 69 - 3;
        bool in = (unsigned)gy < (unsigned)n && (unsigned)gx < (unsigned)n;
        int g = gy * n + gx;
        s_cx[sp] = in ? cx[g] : 0.0f;
        s_cy[sp] = in ? cy[g] : 0.0f;
    }
    for (int sp = tid; sp < 20 * 68; sp += 256) {
        int gy = by0 + sp / 68 - 2, gx = bx0 + sp % 68 - 2;
        bool in = (unsigned)gy < (unsigned)n && (unsigned)gx < (unsigned)n;
        s_rh[sp] = in ? rhs[gy * n + gx] : 0.0f;
    }
    __syncthreads();

    // winv + sweep-1 (u starts at 0 -> u1 = winv * rhs)
    for (int sp = tid; sp < 20 * 68; sp += 256) {
        int y = sp / 68 - 2, x = sp % 68 - 2;
        float cxe = s_cx[IDX69(y, x)], cxw = s_cx[IDX69(y, x - 1)];
        float cyn = s_cy[IDX69(y, x)], cys = s_cy[IDX69(y - 1, x)];
        float wv = __fdividef(OMEGA_W, -((cxe + cxw) + (cyn + cys)) * ih2 - 1.0f);
        s_iv[sp] = wv;
        s_1[sp] = wv * s_rh[sp];
    }
    __syncthreads();

    // sweep-2
    for (int sp = tid; sp < 18 * 66; sp += 256) {
        int y = sp / 66 - 1, x = sp % 66 - 1;
        float um = s_1[IDX68(y, x)];
        float lap = (s_cx[IDX69(y, x)] * (s_1[IDX68(y, x + 1)] - um) -
                     s_cx[IDX69(y, x - 1)] * (um - s_1[IDX68(y, x - 1)])) * ih2 +
                    (s_cy[IDX69(y, x)] * (s_1[IDX68(y + 1, x)] - um) -
                     s_cy[IDX69(y - 1, x)] * (um - s_1[IDX68(y - 1, x)])) * ih2;
        float r = s_rh[IDX68(y, x)] - (lap - um);
        s_2[sp] = um + s_iv[IDX68(y, x)] * r;
    }
    __syncthreads();

    // store u + residual + restrict
    const int x0 = 2 * tx, y0 = 2 * ty;
    const int gx0 = bx0 + x0, gy0 = by0 + y0;
    *reinterpret_cast<float2*>(&udst[gy0 * n + gx0]) =
        make_float2(s_2[IDX66(y0, x0)], s_2[IDX66(y0, x0 + 1)]);
    *reinterpret_cast<float2*>(&udst[(gy0 + 1) * n + gx0]) =
        make_float2(s_2[IDX66(y0 + 1, x0)], s_2[IDX66(y0 + 1, x0 + 1)]);

    float s = 0.0f;
#pragma unroll
    for (int dy = 0; dy < 2; ++dy)
#pragma unroll
        for (int dx = 0; dx < 2; ++dx) {
            int y = y0 + dy, x = x0 + dx;
            float um = s_2[IDX66(y, x)];
            float lap = (s_cx[IDX69(y, x)] * (s_2[IDX66(y, x + 1)] - um) -
                         s_cx[IDX69(y, x - 1)] * (um - s_2[IDX66(y, x - 1)])) * ih2 +
                        (s_cy[IDX69(y, x)] * (s_2[IDX66(y + 1, x)] - um) -
                         s_cy[IDX69(y - 1, x)] * (um - s_2[IDX66(y - 1, x)])) * ih2;
            s += s_rh[IDX68(y, x)] - (lap - um);
        }
    int nc = n >> 1;
    rc[(blockIdx.y * 8 + ty) * nc + blockIdx.x * 32 + tx] = 0.25f * s;
}

// ===========================================================================
// jrr2: nonzero u start. Same as jrr0 but sweep-1 from staged u (halo 3).
// ===========================================================================
__global__ __launch_bounds__(256)
void jrr2_kernel(const float* __restrict__ u,
                 const float* __restrict__ rhs,
                 const float* __restrict__ cx,
                 const float* __restrict__ cy,
                 float* __restrict__ udst,
                 float* __restrict__ rc, int n, float ih2) {
    __shared__ float s_cx[21 * 69], s_cy[21 * 69];
    __shared__ float s_rh[20 * 68], s_iv[20 * 68], s_1[20 * 68];
    __shared__ float s_2[18 * 66];
    __shared__ float s_u[22 * 70];
    const int tx = threadIdx.x, ty = threadIdx.y;
    const int tid = ty * 32 + tx;
    const int bx0 = blockIdx.x * 64, by0 = blockIdx.y * 16;

    for (int sp = tid; sp < 21 * 69; sp += 256) {
        int gy = by0 + sp / 69 - 3, gx = bx0 + sp % 69 - 3;
        bool in = (unsigned)gy < (unsigned)n && (unsigned)gx < (unsigned)n;
        int g = gy * n + gx;
        s_cx[sp] = in ? cx[g] : 0.0f;
        s_cy[sp] = in ? cy[g] : 0.0f;
    }
    for (int sp = tid; sp < 20 * 68; sp += 256) {
        int gy = by0 + sp / 68 - 2, gx = bx0 + sp % 68 - 2;
        bool in = (unsigned)gy < (unsigned)n && (unsigned)gx < (unsigned)n;
        s_rh[sp] = in ? rhs[gy * n + gx] : 0.0f;
    }
    for (int sp = tid; sp < 22 * 70; sp += 256) {
        int gy = by0 + sp / 70 - 3, gx = bx0 + sp % 70 - 3;
        bool in = (unsigned)gy < (unsigned)n && (unsigned)gx < (unsigned)n;
        s_u[sp] = in ? u[gy * n + gx] : 0.0f;
    }
    __syncthreads();

    // winv + sweep-1 from staged u
    for (int sp = tid; sp < 20 * 68; sp += 256) {
        int y = sp / 68 - 2, x = sp % 68 - 2;
        float cxe = s_cx[IDX69(y, x)], cxw = s_cx[IDX69(y, x - 1)];
        float cyn = s_cy[IDX69(y, x)], cys = s_cy[IDX69(y - 1, x)];
        float wv = __fdividef(OMEGA_W, -((cxe + cxw) + (cyn + cys)) * ih2 - 1.0f);
        s_iv[sp] = wv;
        float um = s_u[IDX70(y, x)];
        float lap = (cxe * (s_u[IDX70(y, x + 1)] - um) -
                     cxw * (um - s_u[IDX70(y, x - 1)])) * ih2 +
                    (cyn * (s_u[IDX70(y + 1, x)] - um) -
                     cys * (um - s_u[IDX70(y - 1, x)])) * ih2;
        float r = s_rh[sp] - (lap - um);
        s_1[sp] = um + wv * r;
    }
    __syncthreads();

    // sweep-2
    for (int sp = tid; sp < 18 * 66; sp += 256) {
        int y = sp / 66 - 1, x = sp % 66 - 1;
        float um = s_1[IDX68(y, x)];
        float lap = (s_cx[IDX69(y, x)] * (s_1[IDX68(y, x + 1)] - um) -
                     s_cx[IDX69(y, x - 1)] * (um - s_1[IDX68(y, x - 1)])) * ih2 +
                    (s_cy[IDX69(y, x)] * (s_1[IDX68(y + 1, x)] - um) -
                     s_cy[IDX69(y - 1, x)] * (um - s_1[IDX68(y - 1, x)])) * ih2;
        float r = s_rh[IDX68(y, x)] - (lap - um);
        s_2[sp] = um + s_iv[IDX68(y, x)] * r;
    }
    __syncthreads();

    const int x0 = 2 * tx, y0 = 2 * ty;
    const int gx0 = bx0 + x0, gy0 = by0 + y0;
    *reinterpret_cast<float2*>(&udst[gy0 * n + gx0]) =
        make_float2(s_2[IDX66(y0, x0)], s_2[IDX66(y0, x0 + 1)]);
    *reinterpret_cast<float2*>(&udst[(gy0 + 1) * n + gx0]) =
        make_float2(s_2[IDX66(y0 + 1, x0)], s_2[IDX66(y0 + 1, x0 + 1)]);

    float s = 0.0f;
#pragma unroll
    for (int dy = 0; dy < 2; ++dy)
#pragma unroll
        for (int dx = 0; dx < 2; ++dx) {
            int y = y0 + dy, x = x0 + dx;
            float um = s_2[IDX66(y, x)];
            float lap = (s_cx[IDX69(y, x)] * (s_2[IDX66(y, x + 1)] - um) -
                         s_cx[IDX69(y, x - 1)] * (um - s_2[IDX66(y, x - 1)])) * ih2 +
                        (s_cy[IDX69(y, x)] * (s_2[IDX66(y + 1, x)] - um) -
                         s_cy[IDX69(y - 1, x)] * (um - s_2[IDX66(y - 1, x)])) * ih2;
            s += s_rh[IDX68(y, x)] - (lap - um);
        }
    int nc = n >> 1;
    rc[(blockIdx.y * 8 + ty) * nc + blockIdx.x * 32 + tx] = 0.25f * s;
}

// ===========================================================================
// pjj: {u += prolong(e)} + TWO Jacobi sweeps. Staged u/e/coeffs/rhs.
// ===========================================================================
__global__ __launch_bounds__(256)
void pjj_kernel(const float* __restrict__ u,
                const float* __restrict__ e,
                const float* __restrict__ rhs,
                const float* __restrict__ cx,
                const float* __restrict__ cy,
                float* __restrict__ udst, int n, float ih2) {
    __shared__ float s_cx[21 * 69], s_cy[21 * 69];
    __shared__ float s_rh[20 * 68], s_iv[20 * 68], s_up[20 * 68];
    __shared__ float s_1[18 * 66];
    __shared__ float s_e[12 * 36];
    const int tx = threadIdx.x, ty = threadIdx.y;
    const int tid = ty * 32 + tx;
    const int bx0 = blockIdx.x * 64, by0 = blockIdx.y * 16;
    const int ncc = n >> 1;
    const int bxc = bx0 >> 1, byc = by0 >> 1;

    for (int sp = tid; sp < 21 * 69; sp += 256) {
        int gy = by0 + sp / 69 - 3, gx = bx0 + sp % 69 - 3;
        bool in = (unsigned)gy < (unsigned)n && (unsigned)gx < (unsigned)n;
        int g = gy * n + gx;
        s_cx[sp] = in ? cx[g] : 0.0f;
        s_cy[sp] = in ? cy[g] : 0.0f;
    }
    for (int sp = tid; sp < 20 * 68; sp += 256) {
        int gy = by0 + sp / 68 - 2, gx = bx0 + sp % 68 - 2;
        bool in = (unsigned)gy < (unsigned)n && (unsigned)gx < (unsigned)n;
        int g = gy * n + gx;
        s_rh[sp] = in ? rhs[g] : 0.0f;
        s_up[sp] = in ? u[g] : 0.0f;
    }
    for (int sp = tid; sp < 12 * 36; sp += 256) {
        int jc = byc - 2 + sp / 36, ic = bxc - 2 + sp % 36;
        bool in = (unsigned)jc < (unsigned)ncc && (unsigned)ic < (unsigned)ncc;
        s_e[sp] = in ? e[jc * ncc + ic] : 0.0f;
    }
    __syncthreads();

    // prolong-correct (in place) + winv
    for (int sp = tid; sp < 20 * 68; sp += 256) {
        int y = sp / 68 - 2, x = sp % 68 - 2;
        float cxe = s_cx[IDX69(y, x)], cxw = s_cx[IDX69(y, x - 1)];
        float cyn = s_cy[IDX69(y, x)], cys = s_cy[IDX69(y - 1, x)];
        s_iv[sp] = __fdividef(OMEGA_W, -((cxe + cxw) + (cyn + cys)) * ih2 - 1.0f);

        int gy = by0 + y, gx = bx0 + x;
        float v = 0.0f;
        if ((unsigned)gy < (unsigned)n && (unsigned)gx < (unsigned)n) {
            int jc = gy >> 1, dj = gy & 1;
            int ic = gx >> 1, di = gx & 1;
            int sj = dj ? 1 : -1;
            int si = di ? 1 : -1;
            bool bi = ((unsigned)(ic + si) < (unsigned)ncc);
            bool bj = ((unsigned)(jc + sj) < (unsigned)ncc);
            int ry = jc - byc, rx = ic - bxc;
            float vc = s_e[IDXE(ry, rx)];
            float vsi = s_e[IDXE(ry, rx + si)];
            float vsj = s_e[IDXE(ry + sj, rx)];
            float vd = s_e[IDXE(ry + sj, rx + si)];
            float den = 9.0f + 3.0f * (bi ? 1.0f : 0.0f) + 3.0f * (bj ? 1.0f : 0.0f) +
                        ((bi && bj) ? 1.0f : 0.0f);
            v = s_up[sp] + __fdividef(9.0f * vc + 3.0f * vsi + 3.0f * vsj + vd, den);
        }
        s_up[sp] = v;
    }
    __syncthreads();

    // post-sweep 1 on halo-1
    for (int sp = tid; sp < 18 * 66; sp += 256) {
        int y = sp / 66 - 1, x = sp % 66 - 1;
        float um = s_up[IDX68(y, x)];
        float lap = (s_cx[IDX69(y, x)] * (s_up[IDX68(y, x + 1)] - um) -
                     s_cx[IDX69(y, x - 1)] * (um - s_up[IDX68(y, x - 1)])) * ih2 +
                    (s_cy[IDX69(y, x)] * (s_up[IDX68(y + 1, x)] - um) -
                     s_cy[IDX69(y - 1, x)] * (um - s_up[IDX68(y - 1, x)])) * ih2;
        float r = s_rh[IDX68(y, x)] - (lap - um);
        s_1[sp] = um + s_iv[IDX68(y, x)] * r;
    }
    __syncthreads();

    // post-sweep 2 at owned points + store
    const int x0 = 2 * tx, y0 = 2 * ty;
    const int gx0 = bx0 + x0, gy0 = by0 + y0;
    float o[2][2];
#pragma unroll
    for (int dy = 0; dy < 2; ++dy)
#pragma unroll
        for (int dx = 0; dx < 2; ++dx) {
            int y = y0 + dy, x = x0 + dx;
            float um = s_1[IDX66(y, x)];
            float lap = (s_cx[IDX69(y, x)] * (s_1[IDX66(y, x + 1)] - um) -
                         s_cx[IDX69(y, x - 1)] * (um - s_1[IDX66(y, x - 1)])) * ih2 +
                        (s_cy[IDX69(y, x)] * (s_1[IDX66(y + 1, x)] - um) -
                         s_cy[IDX69(y - 1, x)] * (um - s_1[IDX66(y - 1, x)])) * ih2;
            float r = s_rh[IDX68(y, x)] - (lap - um);
            o[dy][dx] = um + s_iv[IDX68(y, x)] * r;
        }
    *reinterpret_cast<float2*>(&udst[gy0 * n + gx0]) = make_float2(o[0][0], o[0][1]);
    *reinterpret_cast<float2*>(&udst[(gy0 + 1) * n + gx0]) = make_float2(o[1][0], o[1][1]);
}

// ===========================================================================
// L3 v3: 128 CTAs (grid 8x16), 512 threads, owned 32x16, halo 11.
// Coefficients + center-u in REGISTERS; SMEM only ping-pong u (38x54, s=56).
// 11 sweeps/launch; owned region exact (ring at distance 11).
// ===========================================================================
#define L3S 56

__global__ __launch_bounds__(512)
void l3_kernel(const float* __restrict__ uin,
               const float* __restrict__ r3,
               const float* __restrict__ cx3,
               const float* __restrict__ cy3,
               float* __restrict__ uout, int zero_start) {
    __shared__ float ua[38 * L3S], ub[38 * L3S];
    const int tid = threadIdx.x;
    const int gx0 = blockIdx.x * 32 - 11;
    const int gy0 = blockIdx.y * 16 - 11;
    const float ih2 = 0.015625f;

    // fixed point assignment: interior 36x52 = 1872 points, <=4 per thread
    int pidx[4];
    float cae[4], caw[4], can[4], cas[4], cb[4], cu[4];
#pragma unroll
    for (int i = 0; i < 4; ++i) {
        int q = tid + 512 * i;
        pidx[i] = -1;
        cae[i] = caw[i] = can[i] = cas[i] = cb[i] = cu[i] = 0.0f;
        if (q < 36 * 52) {
            int py = q / 52 + 1, px = q % 52 + 1;
            pidx[i] = py * L3S + px;
            int gy = gy0 + py, gx = gx0 + px;
            if ((unsigned)gy < (unsigned)N3 && (unsigned)gx < (unsigned)N3) {
                int idx = gy * N3 + gx;
                float cxe = cx3[idx];
                float cxw = (gx > 0) ? cx3[idx - 1] : 0.0f;
                float cyn = cy3[idx];
                float cys = (gy > 0) ? cy3[idx - N3] : 0.0f;
                float wv = __fdividef(OMEGA_W, -((cxe + cxw) + (cyn + cys)) * ih2 - 1.0f);
                float wi = wv * ih2;
                cae[i] = wi * cxe; caw[i] = wi * cxw;
                can[i] = wi * cyn; cas[i] = wi * cys;
                cb[i] = wv * r3[idx];
            }
        }
    }

    // init BOTH buffers over active 38x54 (ring cells stay at initial value)
    for (int sp = tid; sp < 38 * 54; sp += 512) {
        int py = sp / 54, px = sp % 54;
        int p = py * L3S + px;
        float v = 0.0f;
        if (!zero_start) {
            int gy = gy0 + py, gx = gx0 + px;
            if ((unsigned)gy < (unsigned)N3 && (unsigned)gx < (unsigned)N3)
                v = uin[gy * N3 + gx];
        }
        ua[p] = v; ub[p] = v;
    }
    __syncthreads();
#pragma unroll
    for (int i = 0; i < 4; ++i)
        if (pidx[i] >= 0) cu[i] = ua[pidx[i]];

    float* src = ua;
    float* dst = ub;
#pragma unroll 1
    for (int k = 0; k < 11; ++k) {
#pragma unroll
        for (int i = 0; i < 4; ++i) {
            int p = pidx[i];
            if (p >= 0) {
                float v = (1.0f - OMEGA_W) * cu[i] + cb[i] -
                          (cae[i] * src[p + 1] + caw[i] * src[p - 1] +
                           can[i] * src[p + L3S] + cas[i] * src[p - L3S]);
                dst[p] = v;
                cu[i] = v;
            }
        }
        __syncthreads();
        float* t = src; src = dst; dst = t;
    }

    // store owned 16 rows x 32 cols = exactly one point per thread
    {
        int py = 11 + (tid >> 5), px = 11 + (tid & 31);
        uout[(gy0 + py) * N3 + (gx0 + px)] = src[py * L3S + px];
    }
}

// ---------------------------------------------------------------------------
// Host driver
// ---------------------------------------------------------------------------
extern "C" void kernel_launch(void* const* d_in, const int* in_sizes, int n_in,
                              void* d_out, int out_size) {
    const float* cx[4];
    const float* cy[4];
    const float* rhs;
    if (in_sizes[2] == in_sizes[0]) {
        for (int l = 0; l < 4; ++l) {
            cx[l] = (const float*)d_in[3 * l + 1];
            cy[l] = (const float*)d_in[3 * l + 2];
        }
        rhs = (const float*)d_in[12];
    } else {
        rhs = (const float*)d_in[0];
        for (int l = 0; l < 4; ++l) {
            cx[l] = (const float*)d_in[5 + l];
            cy[l] = (const float*)d_in[9 + l];
        }
    }

    float* uOUT = (float*)d_out;
    float *uB, *uC;
    float *u1a, *u1b, *r1;
    float *u2a, *u2b, *r2;
    float *u3a, *u3b, *r3;
    cudaGetSymbolAddress((void**)&uB, g_u0b);
    cudaGetSymbolAddress((void**)&uC, g_u0c);
    cudaGetSymbolAddress((void**)&u1a, g_u1a);
    cudaGetSymbolAddress((void**)&u1b, g_u1b);
    cudaGetSymbolAddress((void**)&r1, g_r1);
    cudaGetSymbolAddress((void**)&u2a, g_u2a);
    cudaGetSymbolAddress((void**)&u2b, g_u2b);
    cudaGetSymbolAddress((void**)&r2, g_r2);
    cudaGetSymbolAddress((void**)&u3a, g_u3a);
    cudaGetSymbolAddress((void**)&u3b, g_u3b);
    cudaGetSymbolAddress((void**)&r3, g_r3);

    const float ih2_0 = 1.0f, ih2_1 = 0.25f, ih2_2 = 0.0625f;

    dim3 blk(32, 8);
    dim3 t0(N0 / 64, N0 / 16);
    dim3 t1(N1 / 64, N1 / 16);
    dim3 t2(N2 / 64, N2 / 16);
    dim3 g3(8, 16);

    for (int cyc = 0; cyc < 2; ++cyc) {
        // ----- level 0: pre-smooth (2) + residual + restrict -> r1; u -> uB
        if (cyc == 0) {
            jrr0_kernel<<<t0, blk>>>(rhs, cx[0], cy[0], uB, r1, N0, ih2_0);
        } else {
            jrr2_kernel<<<t0, blk>>>(uC, rhs, cx[0], cy[0], uB, r1, N0, ih2_0);
        }

        // ----- level 1: pre (from zero) + residual + restrict -> r2
        jrr0_kernel<<<t1, blk>>>(r1, cx[1], cy[1], u1a, r2, N1, ih2_1);

        // ----- level 2: pre (from zero) + residual + restrict -> r3
        jrr0_kernel<<<t2, blk>>>(r2, cx[2], cy[2], u2a, r3, N2, ih2_2);

        // ----- level 3: 22 sweeps = 2 launches of 11
        l3_kernel<<<g3, 512>>>(r3, r3, cx[3], cy[3], u3a, 1);
        l3_kernel<<<g3, 512>>>(u3a, r3, cx[3], cy[3], u3b, 0);

        // ----- level 2: correct + post (2) -> u2b
        pjj_kernel<<<t2, blk>>>(u2a, u3b, r2, cx[2], cy[2], u2b, N2, ih2_2);

        // ----- level 1: correct + post (2) -> u1b
        pjj_kernel<<<t1, blk>>>(u1a, u2b, r1, cx[1], cy[1], u1b, N1, ih2_1);

        // ----- level 0: correct + post (2)
        if (cyc == 0) {
            pjj_kernel<<<t0, blk>>>(uB, u1b, rhs, cx[0], cy[0], uC, N0, ih2_0);
        } else {
            pjj_kernel<<<t0, blk>>>(uB, u1b, rhs, cx[0], cy[0], uOUT, N0, ih2_0);
        }
    }
}

// round 6
// speedup vs baseline: 1.3787x; 1.3787x over previous
#include <cuda_runtime.h>
#include <cstdint>

#define OMEGA_W 0.9f

#define N0 2048
#define N1 1024
#define N2 512
#define N3 256

// Scratch (device globals — no allocation allowed).
__device__ float g_u0b[N0 * N0];
__device__ float g_u0c[N0 * N0];
__device__ float g_u1a[N1 * N1];
__device__ float g_u1b[N1 * N1];
__device__ float g_r1[N1 * N1];
__device__ float g_u2a[N2 * N2];
__device__ float g_u2b[N2 * N2];
__device__ float g_r2[N2 * N2];
__device__ float g_u3a[N3 * N3];
__device__ float g_u3b[N3 * N3];
__device__ float g_r3[N3 * N3];

// ---------------------------------------------------------------------------
// One Jacobi update at a global point (global-memory reads).
// ---------------------------------------------------------------------------
__device__ __forceinline__ float jac_pt(const float* __restrict__ u,
                                        const float* __restrict__ rhs,
                                        const float* __restrict__ cx,
                                        const float* __restrict__ cy,
                                        int gy, int gx, int n, float ih2) {
    int idx = gy * n + gx;
    float um = u[idx];
    float ue = (gx + 1 < n) ? u[idx + 1] : 0.0f;
    float uw = (gx > 0) ? u[idx - 1] : 0.0f;
    float uN = (gy + 1 < n) ? u[idx + n] : 0.0f;
    float uS = (gy > 0) ? u[idx - n] : 0.0f;
    float cxe = cx[idx];
    float cxw = (gx > 0) ? cx[idx - 1] : 0.0f;
    float cyn = cy[idx];
    float cys = (gy > 0) ? cy[idx - n] : 0.0f;
    float lap = (cxe * (ue - um) - cxw * (um - uw)) * ih2 +
                (cyn * (uN - um) - cys * (um - uS)) * ih2;
    float r = rhs[idx] - (lap - um);
    float diag = -((cxe + cxw) + (cyn + cys)) * ih2 - 1.0f;
    return um + __fdividef(OMEGA_W * r, diag);
}

// ---------------------------------------------------------------------------
// One Jacobi update from an SMEM u-tile (coeffs from global).
// ---------------------------------------------------------------------------
__device__ __forceinline__ float jac_sm(const float* __restrict__ sm,
                                        int ly, int lx, int stride,
                                        const float* __restrict__ rhs,
                                        const float* __restrict__ cx,
                                        const float* __restrict__ cy,
                                        int gy, int gx, int n, float ih2) {
    int lp = ly * stride + lx;
    float um = sm[lp];
    float ue = sm[lp + 1];
    float uw = sm[lp - 1];
    float uN = sm[lp + stride];
    float uS = sm[lp - stride];
    int idx = gy * n + gx;
    float cxe = cx[idx];
    float cxw = (gx > 0) ? cx[idx - 1] : 0.0f;
    float cyn = cy[idx];
    float cys = (gy > 0) ? cy[idx - n] : 0.0f;
    float lap = (cxe * (ue - um) - cxw * (um - uw)) * ih2 +
                (cyn * (uN - um) - cys * (um - uS)) * ih2;
    float r = rhs[idx] - (lap - um);
    float diag = -((cxe + cxw) + (cyn + cys)) * ih2 - 1.0f;
    return um + __fdividef(OMEGA_W * r, diag);
}

// ---------------------------------------------------------------------------
// Residual from an SMEM u-tile.
// ---------------------------------------------------------------------------
__device__ __forceinline__ float resid_sm(const float* __restrict__ sm,
                                          int ly, int lx, int stride,
                                          const float* __restrict__ rhs,
                                          const float* __restrict__ cx,
                                          const float* __restrict__ cy,
                                          int gy, int gx, int n, float ih2) {
    int lp = ly * stride + lx;
    float um = sm[lp];
    float ue = sm[lp + 1];
    float uw = sm[lp - 1];
    float uN = sm[lp + stride];
    float uS = sm[lp - stride];
    int idx = gy * n + gx;
    float cxe = cx[idx];
    float cxw = (gx > 0) ? cx[idx - 1] : 0.0f;
    float cyn = cy[idx];
    float cys = (gy > 0) ? cy[idx - n] : 0.0f;
    float lap = (cxe * (ue - um) - cxw * (um - uw)) * ih2 +
                (cyn * (uN - um) - cys * (um - uS)) * ih2;
    return rhs[idx] - (lap - um);
}

// ===========================================================================
// jrr0: u==0 start. sweep1 (local) -> sweep2 -> residual -> restrict.
// Block (32,8); fine tile 64x16 (thread owns 2x2); coarse out 32x8.
// ===========================================================================
__global__ __launch_bounds__(256)
void jrr0_kernel(const float* __restrict__ rhs,
                 const float* __restrict__ cx,
                 const float* __restrict__ cy,
                 float* __restrict__ udst,
                 float* __restrict__ rc, int n, float ih2) {
    __shared__ float s1[20 * 68];
    __shared__ float su[18 * 66];
    const int tx = threadIdx.x, ty = threadIdx.y;
    const int tid = ty * 32 + tx;
    const int bx0 = blockIdx.x * 64, by0 = blockIdx.y * 16;

    for (int sp = tid; sp < 20 * 68; sp += 256) {
        int py = sp / 68, px = sp % 68;
        int gy = by0 + py - 2, gx = bx0 + px - 2;
        float v = 0.0f;
        if ((unsigned)gy < (unsigned)n && (unsigned)gx < (unsigned)n) {
            int idx = gy * n + gx;
            float cxe = cx[idx];
            float cxw = (gx > 0) ? cx[idx - 1] : 0.0f;
            float cyn = cy[idx];
            float cys = (gy > 0) ? cy[idx - n] : 0.0f;
            float diag = -((cxe + cxw) + (cyn + cys)) * ih2 - 1.0f;
            v = __fdividef(OMEGA_W * rhs[idx], diag);
        }
        s1[sp] = v;
    }
    __syncthreads();

    for (int sp = tid; sp < 18 * 66; sp += 256) {
        int py = sp / 66, px = sp % 66;
        int gy = by0 + py - 1, gx = bx0 + px - 1;
        float v = 0.0f;
        if ((unsigned)gy < (unsigned)n && (unsigned)gx < (unsigned)n)
            v = jac_sm(s1, py + 1, px + 1, 68, rhs, cx, cy, gy, gx, n, ih2);
        su[sp] = v;
    }
    __syncthreads();

    const int gx0 = bx0 + 2 * tx, gy0 = by0 + 2 * ty;
    const int lx0 = 2 * tx + 1, ly0 = 2 * ty + 1;

    *reinterpret_cast<float2*>(&udst[gy0 * n + gx0]) =
        make_float2(su[ly0 * 66 + lx0], su[ly0 * 66 + lx0 + 1]);
    *reinterpret_cast<float2*>(&udst[(gy0 + 1) * n + gx0]) =
        make_float2(su[(ly0 + 1) * 66 + lx0], su[(ly0 + 1) * 66 + lx0 + 1]);

    float s = resid_sm(su, ly0, lx0, 66, rhs, cx, cy, gy0, gx0, n, ih2) +
              resid_sm(su, ly0, lx0 + 1, 66, rhs, cx, cy, gy0, gx0 + 1, n, ih2) +
              resid_sm(su, ly0 + 1, lx0, 66, rhs, cx, cy, gy0 + 1, gx0, n, ih2) +
              resid_sm(su, ly0 + 1, lx0 + 1, 66, rhs, cx, cy, gy0 + 1, gx0 + 1, n, ih2);
    int nc = n >> 1;
    rc[(blockIdx.y * 8 + ty) * nc + blockIdx.x * 32 + tx] = 0.25f * s;
}

// ===========================================================================
// jrr2: nonzero u start. sweep1 (global u, halo2) -> sweep2 -> residual ->
// restrict.
// ===========================================================================
__global__ __launch_bounds__(256)
void jrr2_kernel(const float* __restrict__ u,
                 const float* __restrict__ rhs,
                 const float* __restrict__ cx,
                 const float* __restrict__ cy,
                 float* __restrict__ udst,
                 float* __restrict__ rc, int n, float ih2) {
    __shared__ float s1[20 * 68];
    __shared__ float su[18 * 66];
    const int tx = threadIdx.x, ty = threadIdx.y;
    const int tid = ty * 32 + tx;
    const int bx0 = blockIdx.x * 64, by0 = blockIdx.y * 16;

    for (int sp = tid; sp < 20 * 68; sp += 256) {
        int py = sp / 68, px = sp % 68;
        int gy = by0 + py - 2, gx = bx0 + px - 2;
        float v = 0.0f;
        if ((unsigned)gy < (unsigned)n && (unsigned)gx < (unsigned)n)
            v = jac_pt(u, rhs, cx, cy, gy, gx, n, ih2);
        s1[sp] = v;
    }
    __syncthreads();

    for (int sp = tid; sp < 18 * 66; sp += 256) {
        int py = sp / 66, px = sp % 66;
        int gy = by0 + py - 1, gx = bx0 + px - 1;
        float v = 0.0f;
        if ((unsigned)gy < (unsigned)n && (unsigned)gx < (unsigned)n)
            v = jac_sm(s1, py + 1, px + 1, 68, rhs, cx, cy, gy, gx, n, ih2);
        su[sp] = v;
    }
    __syncthreads();

    const int gx0 = bx0 + 2 * tx, gy0 = by0 + 2 * ty;
    const int lx0 = 2 * tx + 1, ly0 = 2 * ty + 1;

    *reinterpret_cast<float2*>(&udst[gy0 * n + gx0]) =
        make_float2(su[ly0 * 66 + lx0], su[ly0 * 66 + lx0 + 1]);
    *reinterpret_cast<float2*>(&udst[(gy0 + 1) * n + gx0]) =
        make_float2(su[(ly0 + 1) * 66 + lx0], su[(ly0 + 1) * 66 + lx0 + 1]);

    float s = resid_sm(su, ly0, lx0, 66, rhs, cx, cy, gy0, gx0, n, ih2) +
              resid_sm(su, ly0, lx0 + 1, 66, rhs, cx, cy, gy0, gx0 + 1, n, ih2) +
              resid_sm(su, ly0 + 1, lx0, 66, rhs, cx, cy, gy0 + 1, gx0, n, ih2) +
              resid_sm(su, ly0 + 1, lx0 + 1, 66, rhs, cx, cy, gy0 + 1, gx0 + 1, n, ih2);
    int nc = n >> 1;
    rc[(blockIdx.y * 8 + ty) * nc + blockIdx.x * 32 + tx] = 0.25f * s;
}

// ===========================================================================
// pjj: fused {u += prolong(e)} + TWO Jacobi sweeps (complete post-smooth).
// ===========================================================================
__global__ __launch_bounds__(256)
void pjj_kernel(const float* __restrict__ u,
                const float* __restrict__ e,
                const float* __restrict__ rhs,
                const float* __restrict__ cx,
                const float* __restrict__ cy,
                float* __restrict__ udst, int n, float ih2) {
    __shared__ float s1[20 * 68];
    __shared__ float su[18 * 66];
    const int tx = threadIdx.x, ty = threadIdx.y;
    const int tid = ty * 32 + tx;
    const int bx0 = blockIdx.x * 64, by0 = blockIdx.y * 16;
    const int ncc = n >> 1;

    for (int sp = tid; sp < 20 * 68; sp += 256) {
        int py = sp / 68, px = sp % 68;
        int gy = by0 + py - 2, gx = bx0 + px - 2;
        float v = 0.0f;
        if ((unsigned)gy < (unsigned)n && (unsigned)gx < (unsigned)n) {
            int jc = gy >> 1, dj = gy & 1;
            int ic = gx >> 1, di = gx & 1;
            int sj = dj ? 1 : -1;
            int si = di ? 1 : -1;
            bool bi = ((unsigned)(ic + si) < (unsigned)ncc);
            bool bj = ((unsigned)(jc + sj) < (unsigned)ncc);
            float vc = e[jc * ncc + ic];
            float vsi = bi ? e[jc * ncc + ic + si] : 0.0f;
            float vsj = bj ? e[(jc + sj) * ncc + ic] : 0.0f;
            float vd = (bi && bj) ? e[(jc + sj) * ncc + ic + si] : 0.0f;
            float den = 9.0f + 3.0f * (bi ? 1.0f : 0.0f) +
                        3.0f * (bj ? 1.0f : 0.0f) + ((bi && bj) ? 1.0f : 0.0f);
            v = u[gy * n + gx] +
                __fdividef(9.0f * vc + 3.0f * vsi + 3.0f * vsj + vd, den);
        }
        s1[sp] = v;
    }
    __syncthreads();

    for (int sp = tid; sp < 18 * 66; sp += 256) {
        int py = sp / 66, px = sp % 66;
        int gy = by0 + py - 1, gx = bx0 + px - 1;
        float v = 0.0f;
        if ((unsigned)gy < (unsigned)n && (unsigned)gx < (unsigned)n)
            v = jac_sm(s1, py + 1, px + 1, 68, rhs, cx, cy, gy, gx, n, ih2);
        su[sp] = v;
    }
    __syncthreads();

    const int gx0 = bx0 + 2 * tx, gy0 = by0 + 2 * ty;
    const int lx0 = 2 * tx + 1, ly0 = 2 * ty + 1;
    float o00 = jac_sm(su, ly0, lx0, 66, rhs, cx, cy, gy0, gx0, n, ih2);
    float o01 = jac_sm(su, ly0, lx0 + 1, 66, rhs, cx, cy, gy0, gx0 + 1, n, ih2);
    float o10 = jac_sm(su, ly0 + 1, lx0, 66, rhs, cx, cy, gy0 + 1, gx0, n, ih2);
    float o11 = jac_sm(su, ly0 + 1, lx0 + 1, 66, rhs, cx, cy, gy0 + 1, gx0 + 1, n, ih2);
    *reinterpret_cast<float2*>(&udst[gy0 * n + gx0]) = make_float2(o00, o01);
    *reinterpret_cast<float2*>(&udst[(gy0 + 1) * n + gx0]) = make_float2(o10, o11);
}

// ===========================================================================
// L3 v3 (measured 8.9us): 128 CTAs (grid 8x16), 512 threads, owned 32x16,
// halo 11. Coefficients + center-u in REGISTERS; SMEM only ping-pong u.
// 11 sweeps/launch; owned region exact.
// ===========================================================================
#define L3S 56

__global__ __launch_bounds__(512)
void l3_kernel(const float* __restrict__ uin,
               const float* __restrict__ r3,
               const float* __restrict__ cx3,
               const float* __restrict__ cy3,
               float* __restrict__ uout, int zero_start) {
    __shared__ float ua[38 * L3S], ub[38 * L3S];
    const int tid = threadIdx.x;
    const int gx0 = blockIdx.x * 32 - 11;
    const int gy0 = blockIdx.y * 16 - 11;
    const float ih2 = 0.015625f;

    int pidx[4];
    float cae[4], caw[4], can[4], cas[4], cb[4], cu[4];
#pragma unroll
    for (int i = 0; i < 4; ++i) {
        int q = tid + 512 * i;
        pidx[i] = -1;
        cae[i] = caw[i] = can[i] = cas[i] = cb[i] = cu[i] = 0.0f;
        if (q < 36 * 52) {
            int py = q / 52 + 1, px = q % 52 + 1;
            pidx[i] = py * L3S + px;
            int gy = gy0 + py, gx = gx0 + px;
            if ((unsigned)gy < (unsigned)N3 && (unsigned)gx < (unsigned)N3) {
                int idx = gy * N3 + gx;
                float cxe = cx3[idx];
                float cxw = (gx > 0) ? cx3[idx - 1] : 0.0f;
                float cyn = cy3[idx];
                float cys = (gy > 0) ? cy3[idx - N3] : 0.0f;
                float wv = __fdividef(OMEGA_W,
                                      -((cxe + cxw) + (cyn + cys)) * ih2 - 1.0f);
                float wi = wv * ih2;
                cae[i] = wi * cxe; caw[i] = wi * cxw;
                can[i] = wi * cyn; cas[i] = wi * cys;
                cb[i] = wv * r3[idx];
            }
        }
    }

    for (int sp = tid; sp < 38 * 54; sp += 512) {
        int py = sp / 54, px = sp % 54;
        int p = py * L3S + px;
        float v = 0.0f;
        if (!zero_start) {
            int gy = gy0 + py, gx = gx0 + px;
            if ((unsigned)gy < (unsigned)N3 && (unsigned)gx < (unsigned)N3)
                v = uin[gy * N3 + gx];
        }
        ua[p] = v; ub[p] = v;
    }
    __syncthreads();
#pragma unroll
    for (int i = 0; i < 4; ++i)
        if (pidx[i] >= 0) cu[i] = ua[pidx[i]];

    float* src = ua;
    float* dst = ub;
#pragma unroll 1
    for (int k = 0; k < 11; ++k) {
#pragma unroll
        for (int i = 0; i < 4; ++i) {
            int p = pidx[i];
            if (p >= 0) {
                float v = (1.0f - OMEGA_W) * cu[i] + cb[i] -
                          (cae[i] * src[p + 1] + caw[i] * src[p - 1] +
                           can[i] * src[p + L3S] + cas[i] * src[p - L3S]);
                dst[p] = v;
                cu[i] = v;
            }
        }
        __syncthreads();
        float* t = src; src = dst; dst = t;
    }

    {
        int py = 11 + (tid >> 5), px = 11 + (tid & 31);
        uout[(gy0 + py) * N3 + (gx0 + px)] = src[py * L3S + px];
    }
}

// ---------------------------------------------------------------------------
// Host driver
// ---------------------------------------------------------------------------
extern "C" void kernel_launch(void* const* d_in, const int* in_sizes, int n_in,
                              void* d_out, int out_size) {
    const float* cx[4];
    const float* cy[4];
    const float* rhs;
    if (in_sizes[2] == in_sizes[0]) {
        for (int l = 0; l < 4; ++l) {
            cx[l] = (const float*)d_in[3 * l + 1];
            cy[l] = (const float*)d_in[3 * l + 2];
        }
        rhs = (const float*)d_in[12];
    } else {
        rhs = (const float*)d_in[0];
        for (int l = 0; l < 4; ++l) {
            cx[l] = (const float*)d_in[5 + l];
            cy[l] = (const float*)d_in[9 + l];
        }
    }

    float* uOUT = (float*)d_out;
    float *uB, *uC;
    float *u1a, *u1b, *r1;
    float *u2a, *u2b, *r2;
    float *u3a, *u3b, *r3;
    cudaGetSymbolAddress((void**)&uB, g_u0b);
    cudaGetSymbolAddress((void**)&uC, g_u0c);
    cudaGetSymbolAddress((void**)&u1a, g_u1a);
    cudaGetSymbolAddress((void**)&u1b, g_u1b);
    cudaGetSymbolAddress((void**)&r1, g_r1);
    cudaGetSymbolAddress((void**)&u2a, g_u2a);
    cudaGetSymbolAddress((void**)&u2b, g_u2b);
    cudaGetSymbolAddress((void**)&r2, g_r2);
    cudaGetSymbolAddress((void**)&u3a, g_u3a);
    cudaGetSymbolAddress((void**)&u3b, g_u3b);
    cudaGetSymbolAddress((void**)&r3, g_r3);

    const float ih2_0 = 1.0f, ih2_1 = 0.25f, ih2_2 = 0.0625f;

    dim3 blk(32, 8);
    dim3 t0(N0 / 64, N0 / 16);
    dim3 t1(N1 / 64, N1 / 16);
    dim3 t2(N2 / 64, N2 / 16);
    dim3 g3(8, 16);

    for (int cyc = 0; cyc < 2; ++cyc) {
        // ----- level 0: pre-smooth (2) + residual + restrict -> r1; u -> uB
        if (cyc == 0) {
            jrr0_kernel<<<t0, blk>>>(rhs, cx[0], cy[0], uB, r1, N0, ih2_0);
        } else {
            jrr2_kernel<<<t0, blk>>>(uC, rhs, cx[0], cy[0], uB, r1, N0, ih2_0);
        }

        // ----- level 1: pre (from zero) + residual + restrict -> r2
        jrr0_kernel<<<t1, blk>>>(r1, cx[1], cy[1], u1a, r2, N1, ih2_1);

        // ----- level 2: pre (from zero) + residual + restrict -> r3
        jrr0_kernel<<<t2, blk>>>(r2, cx[2], cy[2], u2a, r3, N2, ih2_2);

        // ----- level 3: 22 sweeps = 2 launches of 11
        l3_kernel<<<g3, 512>>>(r3, r3, cx[3], cy[3], u3a, 1);
        l3_kernel<<<g3, 512>>>(u3a, r3, cx[3], cy[3], u3b, 0);

        // ----- level 2: correct + post (2) -> u2b
        pjj_kernel<<<t2, blk>>>(u2a, u3b, r2, cx[2], cy[2], u2b, N2, ih2_2);

        // ----- level 1: correct + post (2) -> u1b
        pjj_kernel<<<t1, blk>>>(u1a, u2b, r1, cx[1], cy[1], u1b, N1, ih2_1);

        // ----- level 0: correct + post (2)
        if (cyc == 0) {
            pjj_kernel<<<t0, blk>>>(uB, u1b, rhs, cx[0], cy[0], uC, N0, ih2_0);
        } else {
            pjj_kernel<<<t0, blk>>>(uB, u1b, rhs, cx[0], cy[0], uOUT, N0, ih2_0);
        }
    }
}